// round 13
// baseline (speedup 1.0000x reference)
#include <cuda_runtime.h>
#include <cuda_bf16.h>
#include <math.h>
#include <stdint.h>

// ---------------------------------------------------------------------------
// Swin block: B=16, C=384, H=W=56, NH=12, WS=7, SS=3, MLP=1536
// GEMMs: mma.sync m16n8k16 bf16 (fp32 accum), 128x128 CTA / 64x32 warp,
// k-chunk 32, reg double-buffer, ldmatrix, fully-unrolled mainloop.
// Attention: fp32, register-blocked. NCHW-direct epilogues.
// ---------------------------------------------------------------------------
#define TOK   50176
#define CCH   384
#define HH    56
#define WW2   56
#define NWIN  1024
#define NTOK  49
#define NHEAD 12
#define HDIM  32
#define MLPD  1536

// Scratch
__device__ __nv_bfloat16 g_xw [TOK * CCH];     // LN1 out (A of QKV)
__device__ float g_q  [TOK * CCH];
__device__ float g_k  [TOK * CCH];
__device__ float g_v  [TOK * CCH];
__device__ __nv_bfloat16 g_ao [TOK * CCH];     // attn out (A of proj)
__device__ float g_x2 [TOK * CCH];
__device__ __nv_bfloat16 g_xn2[TOK * CCH];     // LN2 out (A of fc1)
__device__ __nv_bfloat16 g_h1 [TOK * MLPD];    // gelu out (A of fc2)
// bf16 transposed weights [N][K]
__device__ __nv_bfloat16 g_wt_qkv [1152 * 384];
__device__ __nv_bfloat16 g_wt_proj[384 * 384];
__device__ __nv_bfloat16 g_wt_fc1 [MLPD * 384];
__device__ __nv_bfloat16 g_wt_fc2 [384 * MLPD];

__device__ __forceinline__ uint32_t smem_u32(const void* p) {
    uint32_t a;
    asm("{ .reg .u64 t; cvta.to.shared.u64 t, %1; cvt.u32.u64 %0, t; }"
        : "=r"(a) : "l"(p));
    return a;
}

// ---------------------------------------------------------------------------
// K0: weight prep: W[K][N] fp32 -> Wt[N][K] bf16
// ---------------------------------------------------------------------------
__global__ void __launch_bounds__(256) k_wtprep(const float* __restrict__ W,
                                                __nv_bfloat16* __restrict__ Wt,
                                                int K, int N)
{
    __shared__ float t[32][33];
    const int n0 = blockIdx.x * 32, k0 = blockIdx.y * 32;
    const int lx = threadIdx.x & 31, ly = threadIdx.x >> 5;
#pragma unroll
    for (int i = 0; i < 4; i++)
        t[ly + i * 8][lx] = W[(size_t)(k0 + ly + i * 8) * N + n0 + lx];
    __syncthreads();
#pragma unroll
    for (int i = 0; i < 4; i++)
        Wt[(size_t)(n0 + ly + i * 8) * K + k0 + lx] =
            __float2bfloat16_rn(t[lx][ly + i * 8]);
}

// ---------------------------------------------------------------------------
// bf16 mma GEMM: C = A[M,K] * Bt[N,K]^T, fp32 accum.
// CTA 128x128, 8 warps (2M x 4N), warp 64x32, k-chunk 32, reg double-buffer.
// Crosswise smem As[stage][kg][row][q]; (kg,row) lines contiguous 16B ->
// native ldmatrix.m8n8.b16. NC = chunk count (compile-time, fully unrolled).
// MODE 0: QKV split  1: proj+winrev+residual(x NCHW)  2: fc1+GELU
// MODE 3: fc2+residual -> NCHW output directly
// ---------------------------------------------------------------------------
template <int MODE, int NC>
__global__ void __launch_bounds__(256, 2) k_gemm_bf16(
    const __nv_bfloat16* __restrict__ A, const __nv_bfloat16* __restrict__ Bt,
    const float* __restrict__ bias, float* __restrict__ aux,
    int K, int N)
{
    __shared__ uint32_t As[2][4][128][4];   // 16 KB
    __shared__ uint32_t Bs[2][4][128][4];   // 16 KB

    const int tid = threadIdx.x;
    const int wid = tid >> 5, lane = tid & 31;
    const int gid = lane >> 2, tig = lane & 3;
    const int wm = wid & 1, wn = wid >> 1;       // 2 x 4 warp grid
    const int m0 = blockIdx.y * 128, n0 = blockIdx.x * 128;

    const uint32_t sA = smem_u32(As), sB = smem_u32(Bs);
    const int rowA = wm * 64 + ((lane >> 3) & 1) * 8 + (lane & 7);
    const int kgoA = lane >> 4;
    const int rowB = wn * 32 + (lane & 7);
    const int kgoB = (lane >> 3) & 1;

    float acc[4][4][4];
#pragma unroll
    for (int a = 0; a < 4; a++)
#pragma unroll
        for (int b = 0; b < 4; b++)
#pragma unroll
            for (int c = 0; c < 4; c++) acc[a][b][c] = 0.f;

    const int st_row = tid >> 2;
    const int st_kg = tid & 3;

    uint4 la[2], lb[2];

    auto ldg_chunk = [&](int c) {
#pragma unroll
        for (int t = 0; t < 2; t++) {
            int row = t * 64 + st_row;
            la[t] = *reinterpret_cast<const uint4*>(
                A + (size_t)(m0 + row) * K + c * 32 + st_kg * 8);
            lb[t] = *reinterpret_cast<const uint4*>(
                Bt + (size_t)(n0 + row) * K + c * 32 + st_kg * 8);
        }
    };
    auto sts_chunk = [&](int s) {
#pragma unroll
        for (int t = 0; t < 2; t++) {
            int row = t * 64 + st_row;
            *reinterpret_cast<uint4*>(&As[s][st_kg][row][0]) = la[t];
            *reinterpret_cast<uint4*>(&Bs[s][st_kg][row][0]) = lb[t];
        }
    };

    auto compute = [&](int s) {
#pragma unroll
        for (int ks = 0; ks < 2; ks++) {
            uint32_t af[4][4], bf[4][2];
#pragma unroll
            for (int mi = 0; mi < 4; mi++) {
                uint32_t addr = sA +
                    (uint32_t)(((s * 4 + ks * 2 + kgoA) * 128 +
                                rowA + mi * 16) * 16);
                asm volatile(
                    "ldmatrix.sync.aligned.m8n8.x4.shared.b16 "
                    "{%0,%1,%2,%3}, [%4];"
                    : "=r"(af[mi][0]), "=r"(af[mi][1]),
                      "=r"(af[mi][2]), "=r"(af[mi][3])
                    : "r"(addr));
            }
#pragma unroll
            for (int ni = 0; ni < 4; ni++) {
                uint32_t addr = sB +
                    (uint32_t)(((s * 4 + ks * 2 + kgoB) * 128 +
                                rowB + ni * 8) * 16);
                asm volatile(
                    "ldmatrix.sync.aligned.m8n8.x2.shared.b16 "
                    "{%0,%1}, [%2];"
                    : "=r"(bf[ni][0]), "=r"(bf[ni][1])
                    : "r"(addr));
            }
#pragma unroll
            for (int mi = 0; mi < 4; mi++)
#pragma unroll
                for (int ni = 0; ni < 4; ni++)
                    asm volatile(
                        "mma.sync.aligned.m16n8k16.row.col.f32.bf16.bf16.f32 "
                        "{%0,%1,%2,%3},{%4,%5,%6,%7},{%8,%9},{%0,%1,%2,%3};"
                        : "+f"(acc[mi][ni][0]), "+f"(acc[mi][ni][1]),
                          "+f"(acc[mi][ni][2]), "+f"(acc[mi][ni][3])
                        : "r"(af[mi][0]), "r"(af[mi][1]),
                          "r"(af[mi][2]), "r"(af[mi][3]),
                          "r"(bf[ni][0]), "r"(bf[ni][1]));
        }
    };

    ldg_chunk(0);
    sts_chunk(0);
    __syncthreads();
#pragma unroll
    for (int c = 0; c < NC; c++) {
        if (c + 1 < NC) ldg_chunk(c + 1);
        compute(c & 1);
        if (c + 1 < NC) sts_chunk((c & 1) ^ 1);
        __syncthreads();
    }

    // ---------------- epilogue: fused scatter from accumulators -------------
    const float qscale = 0.17677669529663687f;

    auto store_pair = [&](int m, int n, float vx, float vy) {
        float2 bb = *reinterpret_cast<const float2*>(bias + n);
        vx += bb.x;
        vy += bb.y;
        if (MODE == 0) {
            int tq = n / CCH;
            int rem = n - tq * CCH;
            int head = rem >> 5, hd = rem & 31;
            int win = m / NTOK, tokn = m - win * NTOK;
            float scl = (tq == 0) ? qscale : 1.0f;
            float* dst = (tq == 0) ? g_q : (tq == 1) ? g_k : g_v;
            size_t o = (((size_t)(win * NHEAD + head)) * NTOK + tokn) * HDIM + hd;
            *reinterpret_cast<float2*>(dst + o) = make_float2(vx * scl, vy * scl);
        } else if (MODE == 1) {
            int win = m / NTOK, tokn = m - win * NTOK;
            int b = win >> 6, widx = win & 63;
            int h = (widx >> 3) * 7 + tokn / 7 + 3; if (h >= HH)  h -= HH;
            int w = (widx & 7) * 7 + tokn % 7 + 3;  if (w >= WW2) w -= WW2;
            int hw = h * WW2 + w;
            size_t tk = (size_t)b * (HH * WW2) + hw;
            float rx = __ldg(aux + ((size_t)b * CCH + n) * (HH * WW2) + hw);
            float ry = __ldg(aux + ((size_t)b * CCH + n + 1) * (HH * WW2) + hw);
            *reinterpret_cast<float2*>(g_x2 + tk * CCH + n) =
                make_float2(vx + rx, vy + ry);
        } else if (MODE == 2) {
            vx = 0.5f * vx * (1.0f + erff(vx * 0.70710678118654752f));
            vy = 0.5f * vy * (1.0f + erff(vy * 0.70710678118654752f));
            *reinterpret_cast<__nv_bfloat162*>(g_h1 + (size_t)m * MLPD + n) =
                __floats2bfloat162_rn(vx, vy);
        } else {
            float2 r = *reinterpret_cast<const float2*>(g_x2 + (size_t)m * CCH + n);
            int b = m / (HH * WW2), hw = m - b * (HH * WW2);
            aux[((size_t)b * CCH + n) * (HH * WW2) + hw] = vx + r.x;
            aux[((size_t)b * CCH + n + 1) * (HH * WW2) + hw] = vy + r.y;
        }
    };

#pragma unroll
    for (int mi = 0; mi < 4; mi++) {
#pragma unroll
        for (int ni = 0; ni < 4; ni++) {
            int m = m0 + wm * 64 + mi * 16 + gid;
            int n = n0 + wn * 32 + ni * 8 + tig * 2;
            store_pair(m,     n, acc[mi][ni][0], acc[mi][ni][1]);
            store_pair(m + 8, n, acc[mi][ni][2], acc[mi][ni][3]);
        }
    }
}

// ---------------------------------------------------------------------------
// K1: LN1 + NCHW->NHWC + shifted-window partition (bf16 out only)
// Stats phase: 8 warps x 7 w-columns, lane-parallel over channels.
// Bank-safe: address stride per lane is 57*32 words -> bank = lane*25 % 32,
// gcd(25,32)=1 -> conflict-free.
// ---------------------------------------------------------------------------
__global__ void __launch_bounds__(256) k_ln1_window(
    const float* __restrict__ x, const float* __restrict__ g1,
    const float* __restrict__ b1)
{
    extern __shared__ float sm[];
    __shared__ float smu[56], srs[56];
    const int bh = blockIdx.x;
    const int b = bh / HH, h = bh % HH;
    const int tid = threadIdx.x;
    const int warp = tid >> 5, lane = tid & 31;
    const float* xp = x + (size_t)b * CCH * (HH * WW2) + (size_t)h * WW2;

    for (int idx = tid; idx < CCH * WW2; idx += 256) {
        int c = idx / WW2, w = idx % WW2;
        sm[c * 57 + w] = xp[(size_t)c * (HH * WW2) + w];
    }
    __syncthreads();

    // stats: warp handles w = warp*7 .. warp*7+6
#pragma unroll
    for (int i = 0; i < 7; i++) {
        int w = warp * 7 + i;
        float s = 0.f, s2 = 0.f;
#pragma unroll
        for (int j = 0; j < 12; j++) {
            float t = sm[(lane + j * 32) * 57 + w];
            s += t; s2 += t * t;
        }
#pragma unroll
        for (int o = 16; o; o >>= 1) {
            s  += __shfl_xor_sync(0xffffffffu, s,  o);
            s2 += __shfl_xor_sync(0xffffffffu, s2, o);
        }
        if (lane == 0) {
            float mu = s * (1.0f / CCH);
            smu[w] = mu;
            srs[w] = rsqrtf(s2 * (1.0f / CCH) - mu * mu + 1e-5f);
        }
    }
    __syncthreads();

    int hp = h - 3; if (hp < 0) hp += HH;
    const int wh = hp / 7, rr = hp % 7;
    for (int idx = tid; idx < WW2 * CCH; idx += 256) {
        int w = idx / CCH, c = idx % CCH;
        float val = sm[c * 57 + w];
        float nv = (val - smu[w]) * srs[w] * __ldg(&g1[c]) + __ldg(&b1[c]);
        int wp = w - 3; if (wp < 0) wp += WW2;
        int win = (b * 8 + wh) * 8 + wp / 7;
        g_xw[((size_t)win * NTOK + rr * 7 + wp % 7) * CCH + c] =
            __float2bfloat16_rn(nv);
    }
}

// ---------------------------------------------------------------------------
// K3: windowed attention, register-blocked (fp32)
// ---------------------------------------------------------------------------
__global__ void __launch_bounds__(256) k_attn()
{
    __shared__ float sq[52 * 33], sk[52 * 33], sv[NTOK * 33];
    __shared__ float sS[52 * 52];
    __shared__ int   sid[52];

    const int win = blockIdx.x / NHEAD;
    const int nh  = blockIdx.x % NHEAD;
    const int tid = threadIdx.x;
    const size_t base = ((size_t)(win * NHEAD + nh)) * NTOK * HDIM;

    for (int idx = tid; idx < NTOK * HDIM; idx += 256) {
        int r = idx >> 5, c = idx & 31;
        sq[r * 33 + c] = g_q[base + idx];
        sk[r * 33 + c] = g_k[base + idx];
        sv[r * 33 + c] = g_v[base + idx];
    }
    for (int idx = tid; idx < 3 * 33; idx += 256) {
        sq[NTOK * 33 + idx] = 0.f;
        sk[NTOK * 33 + idx] = 0.f;
    }
    if (tid < 52) {
        int v = 0;
        if (tid < NTOK) {
            int widx = win & 63;
            int hp = (widx >> 3) * 7 + tid / 7;
            int wp = (widx & 7) * 7 + tid % 7;
            int hr = (hp < 49) ? 0 : (hp < 53 ? 1 : 2);
            int wr = (wp < 49) ? 0 : (wp < 53 ? 1 : 2);
            v = hr * 3 + wr;
        }
        sid[tid] = v;
    }
    __syncthreads();

    if (tid < 169) {
        const int iq = (tid / 13) * 4, jq = (tid % 13) * 4;
        float acc[4][4];
#pragma unroll
        for (int r = 0; r < 4; r++)
#pragma unroll
            for (int c = 0; c < 4; c++) acc[r][c] = 0.f;
#pragma unroll
        for (int l = 0; l < HDIM; l++) {
            float qa[4], kb[4];
#pragma unroll
            for (int r = 0; r < 4; r++) qa[r] = sq[(iq + r) * 33 + l];
#pragma unroll
            for (int c = 0; c < 4; c++) kb[c] = sk[(jq + c) * 33 + l];
#pragma unroll
            for (int r = 0; r < 4; r++)
#pragma unroll
                for (int c = 0; c < 4; c++) acc[r][c] += qa[r] * kb[c];
        }
#pragma unroll
        for (int r = 0; r < 4; r++)
#pragma unroll
            for (int c = 0; c < 4; c++) {
                int i = iq + r, j = jq + c;
                float sc = acc[r][c];
                if (sid[i] != sid[j]) sc -= 100.0f;
                sS[i * 52 + j] = sc;
            }
    }
    __syncthreads();

    const int warp = tid >> 5, lane = tid & 31;
    for (int i = warp; i < NTOK; i += 8) {
        float mx = -1e30f;
        for (int j = lane; j < NTOK; j += 32) mx = fmaxf(mx, sS[i * 52 + j]);
#pragma unroll
        for (int o = 16; o; o >>= 1) mx = fmaxf(mx, __shfl_xor_sync(0xffffffffu, mx, o));
        float sum = 0.f;
        for (int j = lane; j < NTOK; j += 32) {
            float e = __expf(sS[i * 52 + j] - mx);
            sS[i * 52 + j] = e;
            sum += e;
        }
#pragma unroll
        for (int o = 16; o; o >>= 1) sum += __shfl_xor_sync(0xffffffffu, sum, o);
        float inv = 1.0f / sum;
        for (int j = lane; j < NTOK; j += 32) sS[i * 52 + j] *= inv;
    }
    __syncthreads();

#pragma unroll
    for (int pass = 0; pass < 2; pass++) {
        int r0 = pass * 32 + warp * 4;
        if (r0 < NTOK) {
            float o[4] = {0.f, 0.f, 0.f, 0.f};
            for (int j = 0; j < NTOK; j++) {
                float v = sv[j * 33 + lane];
#pragma unroll
                for (int r = 0; r < 4; r++)
                    o[r] += sS[(r0 + r) * 52 + j] * v;
            }
#pragma unroll
            for (int r = 0; r < 4; r++) {
                int i = r0 + r;
                if (i < NTOK)
                    g_ao[((size_t)(win * NTOK + i)) * CCH + nh * HDIM + lane] =
                        __float2bfloat16_rn(o[r]);
            }
        }
    }
}

// ---------------------------------------------------------------------------
// K4: LN2 (bf16 out)
// ---------------------------------------------------------------------------
__global__ void __launch_bounds__(256) k_ln2(
    const float* __restrict__ g2, const float* __restrict__ b2)
{
    const int warp = threadIdx.x >> 5, lane = threadIdx.x & 31;
    const size_t tok = (size_t)blockIdx.x * 8 + warp;
    const float* p = g_x2 + tok * CCH;
    float v[12];
    float s = 0.f, s2 = 0.f;
#pragma unroll
    for (int i = 0; i < 12; i++) {
        v[i] = p[lane + i * 32];
        s += v[i]; s2 += v[i] * v[i];
    }
#pragma unroll
    for (int o = 16; o; o >>= 1) {
        s  += __shfl_xor_sync(0xffffffffu, s,  o);
        s2 += __shfl_xor_sync(0xffffffffu, s2, o);
    }
    float mu = s * (1.0f / CCH);
    float rs = rsqrtf(s2 * (1.0f / CCH) - mu * mu + 1e-5f);
    __nv_bfloat16* q = g_xn2 + tok * CCH;
#pragma unroll
    for (int i = 0; i < 12; i++) {
        int c = lane + i * 32;
        q[c] = __float2bfloat16_rn(
            (v[i] - mu) * rs * __ldg(&g2[c]) + __ldg(&b2[c]));
    }
}

// ---------------------------------------------------------------------------
extern "C" void kernel_launch(void* const* d_in, const int* in_sizes, int n_in,
                              void* d_out, int out_size)
{
    const float* x       = (const float*)d_in[0];
    const float* norm1_g = (const float*)d_in[1];
    const float* norm1_b = (const float*)d_in[2];
    const float* qkv_w   = (const float*)d_in[3];
    const float* qkv_b   = (const float*)d_in[4];
    const float* proj_w  = (const float*)d_in[5];
    const float* proj_b  = (const float*)d_in[6];
    const float* norm2_g = (const float*)d_in[7];
    const float* norm2_b = (const float*)d_in[8];
    const float* fc1_w   = (const float*)d_in[9];
    const float* fc1_b   = (const float*)d_in[10];
    const float* fc2_w   = (const float*)d_in[11];
    const float* fc2_b   = (const float*)d_in[12];

    __nv_bfloat16 *p_xw, *p_ao, *p_xn2, *p_h1;
    __nv_bfloat16 *p_wqkv, *p_wproj, *p_wfc1, *p_wfc2;
    cudaGetSymbolAddress((void**)&p_xw,   g_xw);
    cudaGetSymbolAddress((void**)&p_ao,   g_ao);
    cudaGetSymbolAddress((void**)&p_xn2,  g_xn2);
    cudaGetSymbolAddress((void**)&p_h1,   g_h1);
    cudaGetSymbolAddress((void**)&p_wqkv, g_wt_qkv);
    cudaGetSymbolAddress((void**)&p_wproj,g_wt_proj);
    cudaGetSymbolAddress((void**)&p_wfc1, g_wt_fc1);
    cudaGetSymbolAddress((void**)&p_wfc2, g_wt_fc2);

    const int ln1_smem = 384 * 57 * sizeof(float);
    cudaFuncSetAttribute(k_ln1_window,
                         cudaFuncAttributeMaxDynamicSharedMemorySize, ln1_smem);

    // 0) weight prep: transpose + bf16
    k_wtprep<<<dim3(1152 / 32, 384 / 32), 256>>>(qkv_w, p_wqkv, 384, 1152);
    k_wtprep<<<dim3(384 / 32, 384 / 32), 256>>>(proj_w, p_wproj, 384, 384);
    k_wtprep<<<dim3(MLPD / 32, 384 / 32), 256>>>(fc1_w, p_wfc1, 384, MLPD);
    k_wtprep<<<dim3(384 / 32, MLPD / 32), 256>>>(fc2_w, p_wfc2, MLPD, 384);

    // 1) LN1 + transpose + shifted window partition
    k_ln1_window<<<16 * HH, 256, ln1_smem>>>(x, norm1_g, norm1_b);

    // 2) QKV GEMM: [50176,384] x [384,1152]
    k_gemm_bf16<0, 12><<<dim3(1152 / 128, TOK / 128), 256>>>(
        p_xw, p_wqkv, qkv_b, nullptr, 384, 1152);

    // 3) windowed attention
    k_attn<<<NWIN * NHEAD, 256>>>();

    // 4) proj GEMM + window reverse + residual from x (NCHW)
    k_gemm_bf16<1, 12><<<dim3(CCH / 128, TOK / 128), 256>>>(
        p_ao, p_wproj, proj_b, (float*)x, 384, CCH);

    // 5) LN2
    k_ln2<<<TOK / 8, 256>>>(norm2_g, norm2_b);

    // 6) fc1 + GELU
    k_gemm_bf16<2, 12><<<dim3(MLPD / 128, TOK / 128), 256>>>(
        p_xn2, p_wfc1, fc1_b, nullptr, 384, MLPD);

    // 7) fc2 + residual -> NCHW output directly
    k_gemm_bf16<3, 48><<<dim3(CCH / 128, TOK / 128), 256>>>(
        p_h1, p_wfc2, fc2_b, (float*)d_out, 1536, CCH);
}

// round 14
// speedup vs baseline: 1.4666x; 1.4666x over previous
#include <cuda_runtime.h>
#include <cuda_bf16.h>
#include <math.h>
#include <stdint.h>

// ---------------------------------------------------------------------------
// Swin block: B=16, C=384, H=W=56, NH=12, WS=7, SS=3, MLP=1536
// GEMMs: mma.sync m16n8k16 bf16 (fp32 accum), 128x128 CTA / 64x32 warp,
// k-chunk 32, reg double-buffer, ldmatrix, ROLLED mainloop (I$-resident).
// Attention: fp32, register-blocked. NCHW-direct epilogues.
// ---------------------------------------------------------------------------
#define TOK   50176
#define CCH   384
#define HH    56
#define WW2   56
#define NWIN  1024
#define NTOK  49
#define NHEAD 12
#define HDIM  32
#define MLPD  1536

// Scratch
__device__ __nv_bfloat16 g_xw [TOK * CCH];     // LN1 out (A of QKV)
__device__ float g_q  [TOK * CCH];
__device__ float g_k  [TOK * CCH];
__device__ float g_v  [TOK * CCH];
__device__ __nv_bfloat16 g_ao [TOK * CCH];     // attn out (A of proj)
__device__ float g_x2 [TOK * CCH];
__device__ __nv_bfloat16 g_xn2[TOK * CCH];     // LN2 out (A of fc1)
__device__ __nv_bfloat16 g_h1 [TOK * MLPD];    // gelu out (A of fc2)
// bf16 transposed weights [N][K]
__device__ __nv_bfloat16 g_wt_qkv [1152 * 384];
__device__ __nv_bfloat16 g_wt_proj[384 * 384];
__device__ __nv_bfloat16 g_wt_fc1 [MLPD * 384];
__device__ __nv_bfloat16 g_wt_fc2 [384 * MLPD];

__device__ __forceinline__ uint32_t smem_u32(const void* p) {
    uint32_t a;
    asm("{ .reg .u64 t; cvta.to.shared.u64 t, %1; cvt.u32.u64 %0, t; }"
        : "=r"(a) : "l"(p));
    return a;
}

// ---------------------------------------------------------------------------
// K0: weight prep: W[K][N] fp32 -> Wt[N][K] bf16
// ---------------------------------------------------------------------------
__global__ void __launch_bounds__(256) k_wtprep(const float* __restrict__ W,
                                                __nv_bfloat16* __restrict__ Wt,
                                                int K, int N)
{
    __shared__ float t[32][33];
    const int n0 = blockIdx.x * 32, k0 = blockIdx.y * 32;
    const int lx = threadIdx.x & 31, ly = threadIdx.x >> 5;
#pragma unroll
    for (int i = 0; i < 4; i++)
        t[ly + i * 8][lx] = W[(size_t)(k0 + ly + i * 8) * N + n0 + lx];
    __syncthreads();
#pragma unroll
    for (int i = 0; i < 4; i++)
        Wt[(size_t)(n0 + ly + i * 8) * K + k0 + lx] =
            __float2bfloat16_rn(t[lx][ly + i * 8]);
}

// ---------------------------------------------------------------------------
// bf16 mma GEMM: C = A[M,K] * Bt[N,K]^T, fp32 accum.
// CTA 128x128, 8 warps (2M x 4N), warp 64x32, k-chunk 32, reg double-buffer.
// Crosswise smem As[stage][kg][row][q]; (kg,row) lines contiguous 16B ->
// native ldmatrix.m8n8.b16. Rolled mainloop, runtime NC.
// MODE 0: QKV split  1: proj+winrev+residual(x NCHW)  2: fc1+GELU
// MODE 3: fc2+residual -> NCHW output directly
// ---------------------------------------------------------------------------
template <int MODE>
__global__ void __launch_bounds__(256, 2) k_gemm_bf16(
    const __nv_bfloat16* __restrict__ A, const __nv_bfloat16* __restrict__ Bt,
    const float* __restrict__ bias, float* __restrict__ aux,
    int K, int N, int NC)
{
    __shared__ uint32_t As[2][4][128][4];   // 16 KB
    __shared__ uint32_t Bs[2][4][128][4];   // 16 KB

    const int tid = threadIdx.x;
    const int wid = tid >> 5, lane = tid & 31;
    const int gid = lane >> 2, tig = lane & 3;
    const int wm = wid & 1, wn = wid >> 1;       // 2 x 4 warp grid
    const int m0 = blockIdx.y * 128, n0 = blockIdx.x * 128;

    const uint32_t sA = smem_u32(As), sB = smem_u32(Bs);
    const int rowA = wm * 64 + ((lane >> 3) & 1) * 8 + (lane & 7);
    const int kgoA = lane >> 4;
    const int rowB = wn * 32 + (lane & 7);
    const int kgoB = (lane >> 3) & 1;

    float acc[4][4][4];
#pragma unroll
    for (int a = 0; a < 4; a++)
#pragma unroll
        for (int b = 0; b < 4; b++)
#pragma unroll
            for (int c = 0; c < 4; c++) acc[a][b][c] = 0.f;

    const int st_row = tid >> 2;
    const int st_kg = tid & 3;

    uint4 la[2], lb[2];

    auto ldg_chunk = [&](int c) {
#pragma unroll
        for (int t = 0; t < 2; t++) {
            int row = t * 64 + st_row;
            la[t] = *reinterpret_cast<const uint4*>(
                A + (size_t)(m0 + row) * K + c * 32 + st_kg * 8);
            lb[t] = *reinterpret_cast<const uint4*>(
                Bt + (size_t)(n0 + row) * K + c * 32 + st_kg * 8);
        }
    };
    auto sts_chunk = [&](int s) {
#pragma unroll
        for (int t = 0; t < 2; t++) {
            int row = t * 64 + st_row;
            *reinterpret_cast<uint4*>(&As[s][st_kg][row][0]) = la[t];
            *reinterpret_cast<uint4*>(&Bs[s][st_kg][row][0]) = lb[t];
        }
    };

    auto compute = [&](int s) {
#pragma unroll
        for (int ks = 0; ks < 2; ks++) {
            uint32_t af[4][4], bf[4][2];
#pragma unroll
            for (int mi = 0; mi < 4; mi++) {
                uint32_t addr = sA +
                    (uint32_t)(((s * 4 + ks * 2 + kgoA) * 128 +
                                rowA + mi * 16) * 16);
                asm volatile(
                    "ldmatrix.sync.aligned.m8n8.x4.shared.b16 "
                    "{%0,%1,%2,%3}, [%4];"
                    : "=r"(af[mi][0]), "=r"(af[mi][1]),
                      "=r"(af[mi][2]), "=r"(af[mi][3])
                    : "r"(addr));
            }
#pragma unroll
            for (int ni = 0; ni < 4; ni++) {
                uint32_t addr = sB +
                    (uint32_t)(((s * 4 + ks * 2 + kgoB) * 128 +
                                rowB + ni * 8) * 16);
                asm volatile(
                    "ldmatrix.sync.aligned.m8n8.x2.shared.b16 "
                    "{%0,%1}, [%2];"
                    : "=r"(bf[ni][0]), "=r"(bf[ni][1])
                    : "r"(addr));
            }
#pragma unroll
            for (int mi = 0; mi < 4; mi++)
#pragma unroll
                for (int ni = 0; ni < 4; ni++)
                    asm volatile(
                        "mma.sync.aligned.m16n8k16.row.col.f32.bf16.bf16.f32 "
                        "{%0,%1,%2,%3},{%4,%5,%6,%7},{%8,%9},{%0,%1,%2,%3};"
                        : "+f"(acc[mi][ni][0]), "+f"(acc[mi][ni][1]),
                          "+f"(acc[mi][ni][2]), "+f"(acc[mi][ni][3])
                        : "r"(af[mi][0]), "r"(af[mi][1]),
                          "r"(af[mi][2]), "r"(af[mi][3]),
                          "r"(bf[ni][0]), "r"(bf[ni][1]));
        }
    };

    int s = 0;
    ldg_chunk(0);
    sts_chunk(0);
    __syncthreads();
    for (int c = 0; c < NC; c++) {
        if (c + 1 < NC) ldg_chunk(c + 1);
        compute(s);
        if (c + 1 < NC) sts_chunk(s ^ 1);
        __syncthreads();
        s ^= 1;
    }

    // ---------------- epilogue: fused scatter from accumulators -------------
    const float qscale = 0.17677669529663687f;

    auto store_pair = [&](int m, int n, float vx, float vy) {
        float2 bb = *reinterpret_cast<const float2*>(bias + n);
        vx += bb.x;
        vy += bb.y;
        if (MODE == 0) {
            int tq = n / CCH;
            int rem = n - tq * CCH;
            int head = rem >> 5, hd = rem & 31;
            int win = m / NTOK, tokn = m - win * NTOK;
            float scl = (tq == 0) ? qscale : 1.0f;
            float* dst = (tq == 0) ? g_q : (tq == 1) ? g_k : g_v;
            size_t o = (((size_t)(win * NHEAD + head)) * NTOK + tokn) * HDIM + hd;
            *reinterpret_cast<float2*>(dst + o) = make_float2(vx * scl, vy * scl);
        } else if (MODE == 1) {
            int win = m / NTOK, tokn = m - win * NTOK;
            int b = win >> 6, widx = win & 63;
            int h = (widx >> 3) * 7 + tokn / 7 + 3; if (h >= HH)  h -= HH;
            int w = (widx & 7) * 7 + tokn % 7 + 3;  if (w >= WW2) w -= WW2;
            int hw = h * WW2 + w;
            size_t tk = (size_t)b * (HH * WW2) + hw;
            float rx = __ldg(aux + ((size_t)b * CCH + n) * (HH * WW2) + hw);
            float ry = __ldg(aux + ((size_t)b * CCH + n + 1) * (HH * WW2) + hw);
            *reinterpret_cast<float2*>(g_x2 + tk * CCH + n) =
                make_float2(vx + rx, vy + ry);
        } else if (MODE == 2) {
            vx = 0.5f * vx * (1.0f + erff(vx * 0.70710678118654752f));
            vy = 0.5f * vy * (1.0f + erff(vy * 0.70710678118654752f));
            *reinterpret_cast<__nv_bfloat162*>(g_h1 + (size_t)m * MLPD + n) =
                __floats2bfloat162_rn(vx, vy);
        } else {
            float2 r = *reinterpret_cast<const float2*>(g_x2 + (size_t)m * CCH + n);
            int b = m / (HH * WW2), hw = m - b * (HH * WW2);
            aux[((size_t)b * CCH + n) * (HH * WW2) + hw] = vx + r.x;
            aux[((size_t)b * CCH + n + 1) * (HH * WW2) + hw] = vy + r.y;
        }
    };

#pragma unroll
    for (int mi = 0; mi < 4; mi++) {
#pragma unroll
        for (int ni = 0; ni < 4; ni++) {
            int m = m0 + wm * 64 + mi * 16 + gid;
            int n = n0 + wn * 32 + ni * 8 + tig * 2;
            store_pair(m,     n, acc[mi][ni][0], acc[mi][ni][1]);
            store_pair(m + 8, n, acc[mi][ni][2], acc[mi][ni][3]);
        }
    }
}

// ---------------------------------------------------------------------------
// K1: LN1 + NCHW->NHWC + shifted-window partition (bf16 out only)
// Warp-parallel stats: 8 warps x 7 w-columns, lane-parallel over channels.
// ---------------------------------------------------------------------------
__global__ void __launch_bounds__(256) k_ln1_window(
    const float* __restrict__ x, const float* __restrict__ g1,
    const float* __restrict__ b1)
{
    extern __shared__ float sm[];
    __shared__ float smu[56], srs[56];
    const int bh = blockIdx.x;
    const int b = bh / HH, h = bh % HH;
    const int tid = threadIdx.x;
    const int warp = tid >> 5, lane = tid & 31;
    const float* xp = x + (size_t)b * CCH * (HH * WW2) + (size_t)h * WW2;

    for (int idx = tid; idx < CCH * WW2; idx += 256) {
        int c = idx / WW2, w = idx % WW2;
        sm[c * 57 + w] = xp[(size_t)c * (HH * WW2) + w];
    }
    __syncthreads();

#pragma unroll
    for (int i = 0; i < 7; i++) {
        int w = warp * 7 + i;
        float s = 0.f, s2 = 0.f;
#pragma unroll
        for (int j = 0; j < 12; j++) {
            float t = sm[(lane + j * 32) * 57 + w];
            s += t; s2 += t * t;
        }
#pragma unroll
        for (int o = 16; o; o >>= 1) {
            s  += __shfl_xor_sync(0xffffffffu, s,  o);
            s2 += __shfl_xor_sync(0xffffffffu, s2, o);
        }
        if (lane == 0) {
            float mu = s * (1.0f / CCH);
            smu[w] = mu;
            srs[w] = rsqrtf(s2 * (1.0f / CCH) - mu * mu + 1e-5f);
        }
    }
    __syncthreads();

    int hp = h - 3; if (hp < 0) hp += HH;
    const int wh = hp / 7, rr = hp % 7;
    for (int idx = tid; idx < WW2 * CCH; idx += 256) {
        int w = idx / CCH, c = idx % CCH;
        float val = sm[c * 57 + w];
        float nv = (val - smu[w]) * srs[w] * __ldg(&g1[c]) + __ldg(&b1[c]);
        int wp = w - 3; if (wp < 0) wp += WW2;
        int win = (b * 8 + wh) * 8 + wp / 7;
        g_xw[((size_t)win * NTOK + rr * 7 + wp % 7) * CCH + c] =
            __float2bfloat16_rn(nv);
    }
}

// ---------------------------------------------------------------------------
// K3: windowed attention, register-blocked (fp32)
// ---------------------------------------------------------------------------
__global__ void __launch_bounds__(256) k_attn()
{
    __shared__ float sq[52 * 33], sk[52 * 33], sv[NTOK * 33];
    __shared__ float sS[52 * 52];
    __shared__ int   sid[52];

    const int win = blockIdx.x / NHEAD;
    const int nh  = blockIdx.x % NHEAD;
    const int tid = threadIdx.x;
    const size_t base = ((size_t)(win * NHEAD + nh)) * NTOK * HDIM;

    for (int idx = tid; idx < NTOK * HDIM; idx += 256) {
        int r = idx >> 5, c = idx & 31;
        sq[r * 33 + c] = g_q[base + idx];
        sk[r * 33 + c] = g_k[base + idx];
        sv[r * 33 + c] = g_v[base + idx];
    }
    for (int idx = tid; idx < 3 * 33; idx += 256) {
        sq[NTOK * 33 + idx] = 0.f;
        sk[NTOK * 33 + idx] = 0.f;
    }
    if (tid < 52) {
        int v = 0;
        if (tid < NTOK) {
            int widx = win & 63;
            int hp = (widx >> 3) * 7 + tid / 7;
            int wp = (widx & 7) * 7 + tid % 7;
            int hr = (hp < 49) ? 0 : (hp < 53 ? 1 : 2);
            int wr = (wp < 49) ? 0 : (wp < 53 ? 1 : 2);
            v = hr * 3 + wr;
        }
        sid[tid] = v;
    }
    __syncthreads();

    if (tid < 169) {
        const int iq = (tid / 13) * 4, jq = (tid % 13) * 4;
        float acc[4][4];
#pragma unroll
        for (int r = 0; r < 4; r++)
#pragma unroll
            for (int c = 0; c < 4; c++) acc[r][c] = 0.f;
#pragma unroll
        for (int l = 0; l < HDIM; l++) {
            float qa[4], kb[4];
#pragma unroll
            for (int r = 0; r < 4; r++) qa[r] = sq[(iq + r) * 33 + l];
#pragma unroll
            for (int c = 0; c < 4; c++) kb[c] = sk[(jq + c) * 33 + l];
#pragma unroll
            for (int r = 0; r < 4; r++)
#pragma unroll
                for (int c = 0; c < 4; c++) acc[r][c] += qa[r] * kb[c];
        }
#pragma unroll
        for (int r = 0; r < 4; r++)
#pragma unroll
            for (int c = 0; c < 4; c++) {
                int i = iq + r, j = jq + c;
                float sc = acc[r][c];
                if (sid[i] != sid[j]) sc -= 100.0f;
                sS[i * 52 + j] = sc;
            }
    }
    __syncthreads();

    const int warp = tid >> 5, lane = tid & 31;
    for (int i = warp; i < NTOK; i += 8) {
        float mx = -1e30f;
        for (int j = lane; j < NTOK; j += 32) mx = fmaxf(mx, sS[i * 52 + j]);
#pragma unroll
        for (int o = 16; o; o >>= 1) mx = fmaxf(mx, __shfl_xor_sync(0xffffffffu, mx, o));
        float sum = 0.f;
        for (int j = lane; j < NTOK; j += 32) {
            float e = __expf(sS[i * 52 + j] - mx);
            sS[i * 52 + j] = e;
            sum += e;
        }
#pragma unroll
        for (int o = 16; o; o >>= 1) sum += __shfl_xor_sync(0xffffffffu, sum, o);
        float inv = 1.0f / sum;
        for (int j = lane; j < NTOK; j += 32) sS[i * 52 + j] *= inv;
    }
    __syncthreads();

#pragma unroll
    for (int pass = 0; pass < 2; pass++) {
        int r0 = pass * 32 + warp * 4;
        if (r0 < NTOK) {
            float o[4] = {0.f, 0.f, 0.f, 0.f};
            for (int j = 0; j < NTOK; j++) {
                float v = sv[j * 33 + lane];
#pragma unroll
                for (int r = 0; r < 4; r++)
                    o[r] += sS[(r0 + r) * 52 + j] * v;
            }
#pragma unroll
            for (int r = 0; r < 4; r++) {
                int i = r0 + r;
                if (i < NTOK)
                    g_ao[((size_t)(win * NTOK + i)) * CCH + nh * HDIM + lane] =
                        __float2bfloat16_rn(o[r]);
            }
        }
    }
}

// ---------------------------------------------------------------------------
// K4: LN2 (bf16 out)
// ---------------------------------------------------------------------------
__global__ void __launch_bounds__(256) k_ln2(
    const float* __restrict__ g2, const float* __restrict__ b2)
{
    const int warp = threadIdx.x >> 5, lane = threadIdx.x & 31;
    const size_t tok = (size_t)blockIdx.x * 8 + warp;
    const float* p = g_x2 + tok * CCH;
    float v[12];
    float s = 0.f, s2 = 0.f;
#pragma unroll
    for (int i = 0; i < 12; i++) {
        v[i] = p[lane + i * 32];
        s += v[i]; s2 += v[i] * v[i];
    }
#pragma unroll
    for (int o = 16; o; o >>= 1) {
        s  += __shfl_xor_sync(0xffffffffu, s,  o);
        s2 += __shfl_xor_sync(0xffffffffu, s2, o);
    }
    float mu = s * (1.0f / CCH);
    float rs = rsqrtf(s2 * (1.0f / CCH) - mu * mu + 1e-5f);
    __nv_bfloat16* q = g_xn2 + tok * CCH;
#pragma unroll
    for (int i = 0; i < 12; i++) {
        int c = lane + i * 32;
        q[c] = __float2bfloat16_rn(
            (v[i] - mu) * rs * __ldg(&g2[c]) + __ldg(&b2[c]));
    }
}

// ---------------------------------------------------------------------------
extern "C" void kernel_launch(void* const* d_in, const int* in_sizes, int n_in,
                              void* d_out, int out_size)
{
    const float* x       = (const float*)d_in[0];
    const float* norm1_g = (const float*)d_in[1];
    const float* norm1_b = (const float*)d_in[2];
    const float* qkv_w   = (const float*)d_in[3];
    const float* qkv_b   = (const float*)d_in[4];
    const float* proj_w  = (const float*)d_in[5];
    const float* proj_b  = (const float*)d_in[6];
    const float* norm2_g = (const float*)d_in[7];
    const float* norm2_b = (const float*)d_in[8];
    const float* fc1_w   = (const float*)d_in[9];
    const float* fc1_b   = (const float*)d_in[10];
    const float* fc2_w   = (const float*)d_in[11];
    const float* fc2_b   = (const float*)d_in[12];

    __nv_bfloat16 *p_xw, *p_ao, *p_xn2, *p_h1;
    __nv_bfloat16 *p_wqkv, *p_wproj, *p_wfc1, *p_wfc2;
    cudaGetSymbolAddress((void**)&p_xw,   g_xw);
    cudaGetSymbolAddress((void**)&p_ao,   g_ao);
    cudaGetSymbolAddress((void**)&p_xn2,  g_xn2);
    cudaGetSymbolAddress((void**)&p_h1,   g_h1);
    cudaGetSymbolAddress((void**)&p_wqkv, g_wt_qkv);
    cudaGetSymbolAddress((void**)&p_wproj,g_wt_proj);
    cudaGetSymbolAddress((void**)&p_wfc1, g_wt_fc1);
    cudaGetSymbolAddress((void**)&p_wfc2, g_wt_fc2);

    const int ln1_smem = 384 * 57 * sizeof(float);
    cudaFuncSetAttribute(k_ln1_window,
                         cudaFuncAttributeMaxDynamicSharedMemorySize, ln1_smem);

    // 0) weight prep: transpose + bf16
    k_wtprep<<<dim3(1152 / 32, 384 / 32), 256>>>(qkv_w, p_wqkv, 384, 1152);
    k_wtprep<<<dim3(384 / 32, 384 / 32), 256>>>(proj_w, p_wproj, 384, 384);
    k_wtprep<<<dim3(MLPD / 32, 384 / 32), 256>>>(fc1_w, p_wfc1, 384, MLPD);
    k_wtprep<<<dim3(384 / 32, MLPD / 32), 256>>>(fc2_w, p_wfc2, MLPD, 384);

    // 1) LN1 + transpose + shifted window partition
    k_ln1_window<<<16 * HH, 256, ln1_smem>>>(x, norm1_g, norm1_b);

    // 2) QKV GEMM: [50176,384] x [384,1152]
    k_gemm_bf16<0><<<dim3(1152 / 128, TOK / 128), 256>>>(
        p_xw, p_wqkv, qkv_b, nullptr, 384, 1152, 12);

    // 3) windowed attention
    k_attn<<<NWIN * NHEAD, 256>>>();

    // 4) proj GEMM + window reverse + residual from x (NCHW)
    k_gemm_bf16<1><<<dim3(CCH / 128, TOK / 128), 256>>>(
        p_ao, p_wproj, proj_b, (float*)x, 384, CCH, 12);

    // 5) LN2
    k_ln2<<<TOK / 8, 256>>>(norm2_g, norm2_b);

    // 6) fc1 + GELU
    k_gemm_bf16<2><<<dim3(MLPD / 128, TOK / 128), 256>>>(
        p_xn2, p_wfc1, fc1_b, nullptr, 384, MLPD, 12);

    // 7) fc2 + residual -> NCHW output directly
    k_gemm_bf16<3><<<dim3(CCH / 128, TOK / 128), 256>>>(
        p_h1, p_wfc2, fc2_b, (float*)d_out, 1536, CCH, 48);
}

// round 15
// speedup vs baseline: 1.5100x; 1.0296x over previous
#include <cuda_runtime.h>
#include <cuda_bf16.h>
#include <math.h>
#include <stdint.h>

// ---------------------------------------------------------------------------
// Swin block: B=16, C=384, H=W=56, NH=12, WS=7, SS=3, MLP=1536
// GEMMs: mma.sync m16n8k16 bf16 (fp32 accum), 128x128 CTA / 64x32 warp,
// k-chunk 32, reg double-buffer, ldmatrix (A x4, B x4-merged), rolled loop.
// Attention: fp32, register-blocked. NCHW-direct epilogues.
// ---------------------------------------------------------------------------
#define TOK   50176
#define CCH   384
#define HH    56
#define WW2   56
#define NWIN  1024
#define NTOK  49
#define NHEAD 12
#define HDIM  32
#define MLPD  1536

// Scratch
__device__ __nv_bfloat16 g_xw [TOK * CCH];     // LN1 out (A of QKV)
__device__ float g_q  [TOK * CCH];
__device__ float g_k  [TOK * CCH];
__device__ float g_v  [TOK * CCH];
__device__ __nv_bfloat16 g_ao [TOK * CCH];     // attn out (A of proj)
__device__ float g_x2 [TOK * CCH];
__device__ __nv_bfloat16 g_xn2[TOK * CCH];     // LN2 out (A of fc1)
__device__ __nv_bfloat16 g_h1 [TOK * MLPD];    // gelu out (A of fc2)
// bf16 transposed weights [N][K]
__device__ __nv_bfloat16 g_wt_qkv [1152 * 384];
__device__ __nv_bfloat16 g_wt_proj[384 * 384];
__device__ __nv_bfloat16 g_wt_fc1 [MLPD * 384];
__device__ __nv_bfloat16 g_wt_fc2 [384 * MLPD];

__device__ __forceinline__ uint32_t smem_u32(const void* p) {
    uint32_t a;
    asm("{ .reg .u64 t; cvta.to.shared.u64 t, %1; cvt.u32.u64 %0, t; }"
        : "=r"(a) : "l"(p));
    return a;
}

// ---------------------------------------------------------------------------
// K0: merged weight prep: W[K][N] fp32 -> Wt[N][K] bf16 for all 4 weights.
// blockIdx.z selects the weight; out-of-range tiles early-exit.
// ---------------------------------------------------------------------------
__global__ void __launch_bounds__(256) k_wtprep_all(
    const float* __restrict__ qkv_w, const float* __restrict__ proj_w,
    const float* __restrict__ fc1_w, const float* __restrict__ fc2_w)
{
    const float* W;
    __nv_bfloat16* Wt;
    int K, N;
    switch (blockIdx.z) {
        case 0:  W = qkv_w;  Wt = g_wt_qkv;  K = 384;  N = 1152; break;
        case 1:  W = proj_w; Wt = g_wt_proj; K = 384;  N = 384;  break;
        case 2:  W = fc1_w;  Wt = g_wt_fc1;  K = 384;  N = MLPD; break;
        default: W = fc2_w;  Wt = g_wt_fc2;  K = MLPD; N = 384;  break;
    }
    const int n0 = blockIdx.x * 32, k0 = blockIdx.y * 32;
    if (n0 >= N || k0 >= K) return;

    __shared__ float t[32][33];
    const int lx = threadIdx.x & 31, ly = threadIdx.x >> 5;
#pragma unroll
    for (int i = 0; i < 4; i++)
        t[ly + i * 8][lx] = W[(size_t)(k0 + ly + i * 8) * N + n0 + lx];
    __syncthreads();
#pragma unroll
    for (int i = 0; i < 4; i++)
        Wt[(size_t)(n0 + ly + i * 8) * K + k0 + lx] =
            __float2bfloat16_rn(t[lx][ly + i * 8]);
}

// ---------------------------------------------------------------------------
// bf16 mma GEMM: C = A[M,K] * Bt[N,K]^T, fp32 accum.
// CTA 128x128, 8 warps (2M x 4N), warp 64x32, k-chunk 32, reg double-buffer.
// Crosswise smem As[stage][kg][row][q]; (kg,row) lines contiguous 16B ->
// native ldmatrix.m8n8.b16. Rolled mainloop, runtime NC.
// MODE 0: QKV split  1: proj+winrev+residual(x NCHW)  2: fc1+GELU
// MODE 3: fc2+residual -> NCHW output directly
// ---------------------------------------------------------------------------
template <int MODE>
__global__ void __launch_bounds__(256, 2) k_gemm_bf16(
    const __nv_bfloat16* __restrict__ A, const __nv_bfloat16* __restrict__ Bt,
    const float* __restrict__ bias, float* __restrict__ aux,
    int K, int N, int NC)
{
    __shared__ uint32_t As[2][4][128][4];   // 16 KB
    __shared__ uint32_t Bs[2][4][128][4];   // 16 KB

    const int tid = threadIdx.x;
    const int wid = tid >> 5, lane = tid & 31;
    const int gid = lane >> 2, tig = lane & 3;
    const int wm = wid & 1, wn = wid >> 1;       // 2 x 4 warp grid
    const int m0 = blockIdx.y * 128, n0 = blockIdx.x * 128;

    const uint32_t sA = smem_u32(As), sB = smem_u32(Bs);
    const int rowA = wm * 64 + ((lane >> 3) & 1) * 8 + (lane & 7);
    const int kgoA = lane >> 4;
    // B x4-merged: lanes 0-7 -> (kg, ni), 8-15 -> (kg+1, ni),
    //              16-23 -> (kg, ni+1), 24-31 -> (kg+1, ni+1)
    const int rowB4 = wn * 32 + (lane & 7) + ((lane >> 4) << 3);
    const int kgoB = (lane >> 3) & 1;

    float acc[4][4][4];
#pragma unroll
    for (int a = 0; a < 4; a++)
#pragma unroll
        for (int b = 0; b < 4; b++)
#pragma unroll
            for (int c = 0; c < 4; c++) acc[a][b][c] = 0.f;

    const int st_row = tid >> 2;
    const int st_kg = tid & 3;

    uint4 la[2], lb[2];

    auto ldg_chunk = [&](int c) {
#pragma unroll
        for (int t = 0; t < 2; t++) {
            int row = t * 64 + st_row;
            la[t] = *reinterpret_cast<const uint4*>(
                A + (size_t)(m0 + row) * K + c * 32 + st_kg * 8);
            lb[t] = *reinterpret_cast<const uint4*>(
                Bt + (size_t)(n0 + row) * K + c * 32 + st_kg * 8);
        }
    };
    auto sts_chunk = [&](int s) {
#pragma unroll
        for (int t = 0; t < 2; t++) {
            int row = t * 64 + st_row;
            *reinterpret_cast<uint4*>(&As[s][st_kg][row][0]) = la[t];
            *reinterpret_cast<uint4*>(&Bs[s][st_kg][row][0]) = lb[t];
        }
    };

    auto compute = [&](int s) {
#pragma unroll
        for (int ks = 0; ks < 2; ks++) {
            uint32_t af[4][4], bf[4][2];
#pragma unroll
            for (int mi = 0; mi < 4; mi++) {
                uint32_t addr = sA +
                    (uint32_t)(((s * 4 + ks * 2 + kgoA) * 128 +
                                rowA + mi * 16) * 16);
                asm volatile(
                    "ldmatrix.sync.aligned.m8n8.x4.shared.b16 "
                    "{%0,%1,%2,%3}, [%4];"
                    : "=r"(af[mi][0]), "=r"(af[mi][1]),
                      "=r"(af[mi][2]), "=r"(af[mi][3])
                    : "r"(addr));
            }
#pragma unroll
            for (int ni = 0; ni < 4; ni += 2) {
                uint32_t addr = sB +
                    (uint32_t)(((s * 4 + ks * 2 + kgoB) * 128 +
                                rowB4 + ni * 8) * 16);
                asm volatile(
                    "ldmatrix.sync.aligned.m8n8.x4.shared.b16 "
                    "{%0,%1,%2,%3}, [%4];"
                    : "=r"(bf[ni][0]), "=r"(bf[ni][1]),
                      "=r"(bf[ni + 1][0]), "=r"(bf[ni + 1][1])
                    : "r"(addr));
            }
#pragma unroll
            for (int mi = 0; mi < 4; mi++)
#pragma unroll
                for (int ni = 0; ni < 4; ni++)
                    asm volatile(
                        "mma.sync.aligned.m16n8k16.row.col.f32.bf16.bf16.f32 "
                        "{%0,%1,%2,%3},{%4,%5,%6,%7},{%8,%9},{%0,%1,%2,%3};"
                        : "+f"(acc[mi][ni][0]), "+f"(acc[mi][ni][1]),
                          "+f"(acc[mi][ni][2]), "+f"(acc[mi][ni][3])
                        : "r"(af[mi][0]), "r"(af[mi][1]),
                          "r"(af[mi][2]), "r"(af[mi][3]),
                          "r"(bf[ni][0]), "r"(bf[ni][1]));
        }
    };

    int s = 0;
    ldg_chunk(0);
    sts_chunk(0);
    __syncthreads();
    for (int c = 0; c < NC; c++) {
        if (c + 1 < NC) ldg_chunk(c + 1);
        compute(s);
        if (c + 1 < NC) sts_chunk(s ^ 1);
        __syncthreads();
        s ^= 1;
    }

    // ---------------- epilogue: fused scatter from accumulators -------------
    const float qscale = 0.17677669529663687f;

    auto store_pair = [&](int m, int n, float vx, float vy) {
        vx += __ldg(&bias[n]);
        vy += __ldg(&bias[n + 1]);
        if (MODE == 0) {
            int tq = n / CCH;
            int rem = n - tq * CCH;
            int head = rem >> 5, hd = rem & 31;
            int win = m / NTOK, tokn = m - win * NTOK;
            float scl = (tq == 0) ? qscale : 1.0f;
            float* dst = (tq == 0) ? g_q : (tq == 1) ? g_k : g_v;
            size_t o = (((size_t)(win * NHEAD + head)) * NTOK + tokn) * HDIM + hd;
            *reinterpret_cast<float2*>(dst + o) = make_float2(vx * scl, vy * scl);
        } else if (MODE == 1) {
            int win = m / NTOK, tokn = m - win * NTOK;
            int b = win >> 6, widx = win & 63;
            int h = (widx >> 3) * 7 + tokn / 7 + 3; if (h >= HH)  h -= HH;
            int w = (widx & 7) * 7 + tokn % 7 + 3;  if (w >= WW2) w -= WW2;
            int hw = h * WW2 + w;
            size_t tk = (size_t)b * (HH * WW2) + hw;
            float rx = __ldg(aux + ((size_t)b * CCH + n) * (HH * WW2) + hw);
            float ry = __ldg(aux + ((size_t)b * CCH + n + 1) * (HH * WW2) + hw);
            *reinterpret_cast<float2*>(g_x2 + tk * CCH + n) =
                make_float2(vx + rx, vy + ry);
        } else if (MODE == 2) {
            vx = 0.5f * vx * (1.0f + erff(vx * 0.70710678118654752f));
            vy = 0.5f * vy * (1.0f + erff(vy * 0.70710678118654752f));
            *reinterpret_cast<__nv_bfloat162*>(g_h1 + (size_t)m * MLPD + n) =
                __floats2bfloat162_rn(vx, vy);
        } else {
            float2 r = *reinterpret_cast<const float2*>(g_x2 + (size_t)m * CCH + n);
            int b = m / (HH * WW2), hw = m - b * (HH * WW2);
            aux[((size_t)b * CCH + n) * (HH * WW2) + hw] = vx + r.x;
            aux[((size_t)b * CCH + n + 1) * (HH * WW2) + hw] = vy + r.y;
        }
    };

#pragma unroll
    for (int mi = 0; mi < 4; mi++) {
#pragma unroll
        for (int ni = 0; ni < 4; ni++) {
            int m = m0 + wm * 64 + mi * 16 + gid;
            int n = n0 + wn * 32 + ni * 8 + tig * 2;
            store_pair(m,     n, acc[mi][ni][0], acc[mi][ni][1]);
            store_pair(m + 8, n, acc[mi][ni][2], acc[mi][ni][3]);
        }
    }
}

// ---------------------------------------------------------------------------
// K1: LN1 + NCHW->NHWC + shifted-window partition (bf16 out only)
// Warp-parallel stats: 8 warps x 7 w-columns, lane-parallel over channels.
// ---------------------------------------------------------------------------
__global__ void __launch_bounds__(256) k_ln1_window(
    const float* __restrict__ x, const float* __restrict__ g1,
    const float* __restrict__ b1)
{
    extern __shared__ float sm[];
    __shared__ float smu[56], srs[56];
    const int bh = blockIdx.x;
    const int b = bh / HH, h = bh % HH;
    const int tid = threadIdx.x;
    const int warp = tid >> 5, lane = tid & 31;
    const float* xp = x + (size_t)b * CCH * (HH * WW2) + (size_t)h * WW2;

    for (int idx = tid; idx < CCH * WW2; idx += 256) {
        int c = idx / WW2, w = idx % WW2;
        sm[c * 57 + w] = xp[(size_t)c * (HH * WW2) + w];
    }
    __syncthreads();

#pragma unroll
    for (int i = 0; i < 7; i++) {
        int w = warp * 7 + i;
        float s = 0.f, s2 = 0.f;
#pragma unroll
        for (int j = 0; j < 12; j++) {
            float t = sm[(lane + j * 32) * 57 + w];
            s += t; s2 += t * t;
        }
#pragma unroll
        for (int o = 16; o; o >>= 1) {
            s  += __shfl_xor_sync(0xffffffffu, s,  o);
            s2 += __shfl_xor_sync(0xffffffffu, s2, o);
        }
        if (lane == 0) {
            float mu = s * (1.0f / CCH);
            smu[w] = mu;
            srs[w] = rsqrtf(s2 * (1.0f / CCH) - mu * mu + 1e-5f);
        }
    }
    __syncthreads();

    int hp = h - 3; if (hp < 0) hp += HH;
    const int wh = hp / 7, rr = hp % 7;
    for (int idx = tid; idx < WW2 * CCH; idx += 256) {
        int w = idx / CCH, c = idx % CCH;
        float val = sm[c * 57 + w];
        float nv = (val - smu[w]) * srs[w] * __ldg(&g1[c]) + __ldg(&b1[c]);
        int wp = w - 3; if (wp < 0) wp += WW2;
        int win = (b * 8 + wh) * 8 + wp / 7;
        g_xw[((size_t)win * NTOK + rr * 7 + wp % 7) * CCH + c] =
            __float2bfloat16_rn(nv);
    }
}

// ---------------------------------------------------------------------------
// K3: windowed attention, register-blocked (fp32)
// ---------------------------------------------------------------------------
__global__ void __launch_bounds__(256) k_attn()
{
    __shared__ float sq[52 * 33], sk[52 * 33], sv[NTOK * 33];
    __shared__ float sS[52 * 52];
    __shared__ int   sid[52];

    const int win = blockIdx.x / NHEAD;
    const int nh  = blockIdx.x % NHEAD;
    const int tid = threadIdx.x;
    const size_t base = ((size_t)(win * NHEAD + nh)) * NTOK * HDIM;

    for (int idx = tid; idx < NTOK * HDIM; idx += 256) {
        int r = idx >> 5, c = idx & 31;
        sq[r * 33 + c] = g_q[base + idx];
        sk[r * 33 + c] = g_k[base + idx];
        sv[r * 33 + c] = g_v[base + idx];
    }
    for (int idx = tid; idx < 3 * 33; idx += 256) {
        sq[NTOK * 33 + idx] = 0.f;
        sk[NTOK * 33 + idx] = 0.f;
    }
    if (tid < 52) {
        int v = 0;
        if (tid < NTOK) {
            int widx = win & 63;
            int hp = (widx >> 3) * 7 + tid / 7;
            int wp = (widx & 7) * 7 + tid % 7;
            int hr = (hp < 49) ? 0 : (hp < 53 ? 1 : 2);
            int wr = (wp < 49) ? 0 : (wp < 53 ? 1 : 2);
            v = hr * 3 + wr;
        }
        sid[tid] = v;
    }
    __syncthreads();

    if (tid < 169) {
        const int iq = (tid / 13) * 4, jq = (tid % 13) * 4;
        float acc[4][4];
#pragma unroll
        for (int r = 0; r < 4; r++)
#pragma unroll
            for (int c = 0; c < 4; c++) acc[r][c] = 0.f;
#pragma unroll
        for (int l = 0; l < HDIM; l++) {
            float qa[4], kb[4];
#pragma unroll
            for (int r = 0; r < 4; r++) qa[r] = sq[(iq + r) * 33 + l];
#pragma unroll
            for (int c = 0; c < 4; c++) kb[c] = sk[(jq + c) * 33 + l];
#pragma unroll
            for (int r = 0; r < 4; r++)
#pragma unroll
                for (int c = 0; c < 4; c++) acc[r][c] += qa[r] * kb[c];
        }
#pragma unroll
        for (int r = 0; r < 4; r++)
#pragma unroll
            for (int c = 0; c < 4; c++) {
                int i = iq + r, j = jq + c;
                float sc = acc[r][c];
                if (sid[i] != sid[j]) sc -= 100.0f;
                sS[i * 52 + j] = sc;
            }
    }
    __syncthreads();

    const int warp = tid >> 5, lane = tid & 31;
    for (int i = warp; i < NTOK; i += 8) {
        float mx = -1e30f;
        for (int j = lane; j < NTOK; j += 32) mx = fmaxf(mx, sS[i * 52 + j]);
#pragma unroll
        for (int o = 16; o; o >>= 1) mx = fmaxf(mx, __shfl_xor_sync(0xffffffffu, mx, o));
        float sum = 0.f;
        for (int j = lane; j < NTOK; j += 32) {
            float e = __expf(sS[i * 52 + j] - mx);
            sS[i * 52 + j] = e;
            sum += e;
        }
#pragma unroll
        for (int o = 16; o; o >>= 1) sum += __shfl_xor_sync(0xffffffffu, sum, o);
        float inv = 1.0f / sum;
        for (int j = lane; j < NTOK; j += 32) sS[i * 52 + j] *= inv;
    }
    __syncthreads();

#pragma unroll
    for (int pass = 0; pass < 2; pass++) {
        int r0 = pass * 32 + warp * 4;
        if (r0 < NTOK) {
            float o[4] = {0.f, 0.f, 0.f, 0.f};
            for (int j = 0; j < NTOK; j++) {
                float v = sv[j * 33 + lane];
#pragma unroll
                for (int r = 0; r < 4; r++)
                    o[r] += sS[(r0 + r) * 52 + j] * v;
            }
#pragma unroll
            for (int r = 0; r < 4; r++) {
                int i = r0 + r;
                if (i < NTOK)
                    g_ao[((size_t)(win * NTOK + i)) * CCH + nh * HDIM + lane] =
                        __float2bfloat16_rn(o[r]);
            }
        }
    }
}

// ---------------------------------------------------------------------------
// K4: LN2 (bf16 out)
// ---------------------------------------------------------------------------
__global__ void __launch_bounds__(256) k_ln2(
    const float* __restrict__ g2, const float* __restrict__ b2)
{
    const int warp = threadIdx.x >> 5, lane = threadIdx.x & 31;
    const size_t tok = (size_t)blockIdx.x * 8 + warp;
    const float* p = g_x2 + tok * CCH;
    float v[12];
    float s = 0.f, s2 = 0.f;
#pragma unroll
    for (int i = 0; i < 12; i++) {
        v[i] = p[lane + i * 32];
        s += v[i]; s2 += v[i] * v[i];
    }
#pragma unroll
    for (int o = 16; o; o >>= 1) {
        s  += __shfl_xor_sync(0xffffffffu, s,  o);
        s2 += __shfl_xor_sync(0xffffffffu, s2, o);
    }
    float mu = s * (1.0f / CCH);
    float rs = rsqrtf(s2 * (1.0f / CCH) - mu * mu + 1e-5f);
    __nv_bfloat16* q = g_xn2 + tok * CCH;
#pragma unroll
    for (int i = 0; i < 12; i++) {
        int c = lane + i * 32;
        q[c] = __float2bfloat16_rn(
            (v[i] - mu) * rs * __ldg(&g2[c]) + __ldg(&b2[c]));
    }
}

// ---------------------------------------------------------------------------
extern "C" void kernel_launch(void* const* d_in, const int* in_sizes, int n_in,
                              void* d_out, int out_size)
{
    const float* x       = (const float*)d_in[0];
    const float* norm1_g = (const float*)d_in[1];
    const float* norm1_b = (const float*)d_in[2];
    const float* qkv_w   = (const float*)d_in[3];
    const float* qkv_b   = (const float*)d_in[4];
    const float* proj_w  = (const float*)d_in[5];
    const float* proj_b  = (const float*)d_in[6];
    const float* norm2_g = (const float*)d_in[7];
    const float* norm2_b = (const float*)d_in[8];
    const float* fc1_w   = (const float*)d_in[9];
    const float* fc1_b   = (const float*)d_in[10];
    const float* fc2_w   = (const float*)d_in[11];
    const float* fc2_b   = (const float*)d_in[12];

    __nv_bfloat16 *p_xw, *p_ao, *p_xn2, *p_h1;
    __nv_bfloat16 *p_wqkv, *p_wproj, *p_wfc1, *p_wfc2;
    cudaGetSymbolAddress((void**)&p_xw,   g_xw);
    cudaGetSymbolAddress((void**)&p_ao,   g_ao);
    cudaGetSymbolAddress((void**)&p_xn2,  g_xn2);
    cudaGetSymbolAddress((void**)&p_h1,   g_h1);
    cudaGetSymbolAddress((void**)&p_wqkv, g_wt_qkv);
    cudaGetSymbolAddress((void**)&p_wproj,g_wt_proj);
    cudaGetSymbolAddress((void**)&p_wfc1, g_wt_fc1);
    cudaGetSymbolAddress((void**)&p_wfc2, g_wt_fc2);

    const int ln1_smem = 384 * 57 * sizeof(float);
    cudaFuncSetAttribute(k_ln1_window,
                         cudaFuncAttributeMaxDynamicSharedMemorySize, ln1_smem);

    // 0) merged weight prep: transpose + bf16 (4 weights, one launch)
    k_wtprep_all<<<dim3(48, 48, 4), 256>>>(qkv_w, proj_w, fc1_w, fc2_w);

    // 1) LN1 + transpose + shifted window partition
    k_ln1_window<<<16 * HH, 256, ln1_smem>>>(x, norm1_g, norm1_b);

    // 2) QKV GEMM: [50176,384] x [384,1152]
    k_gemm_bf16<0><<<dim3(1152 / 128, TOK / 128), 256>>>(
        p_xw, p_wqkv, qkv_b, nullptr, 384, 1152, 12);

    // 3) windowed attention
    k_attn<<<NWIN * NHEAD, 256>>>();

    // 4) proj GEMM + window reverse + residual from x (NCHW)
    k_gemm_bf16<1><<<dim3(CCH / 128, TOK / 128), 256>>>(
        p_ao, p_wproj, proj_b, (float*)x, 384, CCH, 12);

    // 5) LN2
    k_ln2<<<TOK / 8, 256>>>(norm2_g, norm2_b);

    // 6) fc1 + GELU
    k_gemm_bf16<2><<<dim3(MLPD / 128, TOK / 128), 256>>>(
        p_xn2, p_wfc1, fc1_b, nullptr, 384, MLPD, 12);

    // 7) fc2 + residual -> NCHW output directly
    k_gemm_bf16<3><<<dim3(CCH / 128, TOK / 128), 256>>>(
        p_h1, p_wfc2, fc2_b, (float*)d_out, 1536, CCH, 48);
}

// round 16
// speedup vs baseline: 1.5667x; 1.0376x over previous
#include <cuda_runtime.h>
#include <cuda_bf16.h>
#include <math.h>
#include <stdint.h>

// ---------------------------------------------------------------------------
// Swin block: B=16, C=384, H=W=56, NH=12, WS=7, SS=3, MLP=1536
// GEMMs: mma.sync m16n8k16 bf16 (fp32 accum), 128x128 CTA / 64x32 warp,
// k-chunk 32, reg double-buffer, ldmatrix (A x4, B x4-merged), rolled loop.
// Attention: fp32, float4-vectorized smem (QK^T 4x4 reg tile, PV 8-row warp).
// NCHW-direct epilogues.
// ---------------------------------------------------------------------------
#define TOK   50176
#define CCH   384
#define HH    56
#define WW2   56
#define NWIN  1024
#define NTOK  49
#define NHEAD 12
#define HDIM  32
#define MLPD  1536

// Scratch
__device__ __nv_bfloat16 g_xw [TOK * CCH];     // LN1 out (A of QKV)
__device__ float g_q  [TOK * CCH];
__device__ float g_k  [TOK * CCH];
__device__ float g_v  [TOK * CCH];
__device__ __nv_bfloat16 g_ao [TOK * CCH];     // attn out (A of proj)
__device__ float g_x2 [TOK * CCH];
__device__ __nv_bfloat16 g_xn2[TOK * CCH];     // LN2 out (A of fc1)
__device__ __nv_bfloat16 g_h1 [TOK * MLPD];    // gelu out (A of fc2)
// bf16 transposed weights [N][K]
__device__ __nv_bfloat16 g_wt_qkv [1152 * 384];
__device__ __nv_bfloat16 g_wt_proj[384 * 384];
__device__ __nv_bfloat16 g_wt_fc1 [MLPD * 384];
__device__ __nv_bfloat16 g_wt_fc2 [384 * MLPD];

__device__ __forceinline__ uint32_t smem_u32(const void* p) {
    uint32_t a;
    asm("{ .reg .u64 t; cvta.to.shared.u64 t, %1; cvt.u32.u64 %0, t; }"
        : "=r"(a) : "l"(p));
    return a;
}

// ---------------------------------------------------------------------------
// K0: merged weight prep: W[K][N] fp32 -> Wt[N][K] bf16 for all 4 weights.
// ---------------------------------------------------------------------------
__global__ void __launch_bounds__(256) k_wtprep_all(
    const float* __restrict__ qkv_w, const float* __restrict__ proj_w,
    const float* __restrict__ fc1_w, const float* __restrict__ fc2_w)
{
    const float* W;
    __nv_bfloat16* Wt;
    int K, N;
    switch (blockIdx.z) {
        case 0:  W = qkv_w;  Wt = g_wt_qkv;  K = 384;  N = 1152; break;
        case 1:  W = proj_w; Wt = g_wt_proj; K = 384;  N = 384;  break;
        case 2:  W = fc1_w;  Wt = g_wt_fc1;  K = 384;  N = MLPD; break;
        default: W = fc2_w;  Wt = g_wt_fc2;  K = MLPD; N = 384;  break;
    }
    const int n0 = blockIdx.x * 32, k0 = blockIdx.y * 32;
    if (n0 >= N || k0 >= K) return;

    __shared__ float t[32][33];
    const int lx = threadIdx.x & 31, ly = threadIdx.x >> 5;
#pragma unroll
    for (int i = 0; i < 4; i++)
        t[ly + i * 8][lx] = W[(size_t)(k0 + ly + i * 8) * N + n0 + lx];
    __syncthreads();
#pragma unroll
    for (int i = 0; i < 4; i++)
        Wt[(size_t)(n0 + ly + i * 8) * K + k0 + lx] =
            __float2bfloat16_rn(t[lx][ly + i * 8]);
}

// ---------------------------------------------------------------------------
// bf16 mma GEMM (R15 skeleton, unchanged)
// ---------------------------------------------------------------------------
template <int MODE>
__global__ void __launch_bounds__(256, 2) k_gemm_bf16(
    const __nv_bfloat16* __restrict__ A, const __nv_bfloat16* __restrict__ Bt,
    const float* __restrict__ bias, float* __restrict__ aux,
    int K, int N, int NC)
{
    __shared__ uint32_t As[2][4][128][4];   // 16 KB
    __shared__ uint32_t Bs[2][4][128][4];   // 16 KB

    const int tid = threadIdx.x;
    const int wid = tid >> 5, lane = tid & 31;
    const int gid = lane >> 2, tig = lane & 3;
    const int wm = wid & 1, wn = wid >> 1;       // 2 x 4 warp grid
    const int m0 = blockIdx.y * 128, n0 = blockIdx.x * 128;

    const uint32_t sA = smem_u32(As), sB = smem_u32(Bs);
    const int rowA = wm * 64 + ((lane >> 3) & 1) * 8 + (lane & 7);
    const int kgoA = lane >> 4;
    const int rowB4 = wn * 32 + (lane & 7) + ((lane >> 4) << 3);
    const int kgoB = (lane >> 3) & 1;

    float acc[4][4][4];
#pragma unroll
    for (int a = 0; a < 4; a++)
#pragma unroll
        for (int b = 0; b < 4; b++)
#pragma unroll
            for (int c = 0; c < 4; c++) acc[a][b][c] = 0.f;

    const int st_row = tid >> 2;
    const int st_kg = tid & 3;

    uint4 la[2], lb[2];

    auto ldg_chunk = [&](int c) {
#pragma unroll
        for (int t = 0; t < 2; t++) {
            int row = t * 64 + st_row;
            la[t] = *reinterpret_cast<const uint4*>(
                A + (size_t)(m0 + row) * K + c * 32 + st_kg * 8);
            lb[t] = *reinterpret_cast<const uint4*>(
                Bt + (size_t)(n0 + row) * K + c * 32 + st_kg * 8);
        }
    };
    auto sts_chunk = [&](int s) {
#pragma unroll
        for (int t = 0; t < 2; t++) {
            int row = t * 64 + st_row;
            *reinterpret_cast<uint4*>(&As[s][st_kg][row][0]) = la[t];
            *reinterpret_cast<uint4*>(&Bs[s][st_kg][row][0]) = lb[t];
        }
    };

    auto compute = [&](int s) {
#pragma unroll
        for (int ks = 0; ks < 2; ks++) {
            uint32_t af[4][4], bf[4][2];
#pragma unroll
            for (int mi = 0; mi < 4; mi++) {
                uint32_t addr = sA +
                    (uint32_t)(((s * 4 + ks * 2 + kgoA) * 128 +
                                rowA + mi * 16) * 16);
                asm volatile(
                    "ldmatrix.sync.aligned.m8n8.x4.shared.b16 "
                    "{%0,%1,%2,%3}, [%4];"
                    : "=r"(af[mi][0]), "=r"(af[mi][1]),
                      "=r"(af[mi][2]), "=r"(af[mi][3])
                    : "r"(addr));
            }
#pragma unroll
            for (int ni = 0; ni < 4; ni += 2) {
                uint32_t addr = sB +
                    (uint32_t)(((s * 4 + ks * 2 + kgoB) * 128 +
                                rowB4 + ni * 8) * 16);
                asm volatile(
                    "ldmatrix.sync.aligned.m8n8.x4.shared.b16 "
                    "{%0,%1,%2,%3}, [%4];"
                    : "=r"(bf[ni][0]), "=r"(bf[ni][1]),
                      "=r"(bf[ni + 1][0]), "=r"(bf[ni + 1][1])
                    : "r"(addr));
            }
#pragma unroll
            for (int mi = 0; mi < 4; mi++)
#pragma unroll
                for (int ni = 0; ni < 4; ni++)
                    asm volatile(
                        "mma.sync.aligned.m16n8k16.row.col.f32.bf16.bf16.f32 "
                        "{%0,%1,%2,%3},{%4,%5,%6,%7},{%8,%9},{%0,%1,%2,%3};"
                        : "+f"(acc[mi][ni][0]), "+f"(acc[mi][ni][1]),
                          "+f"(acc[mi][ni][2]), "+f"(acc[mi][ni][3])
                        : "r"(af[mi][0]), "r"(af[mi][1]),
                          "r"(af[mi][2]), "r"(af[mi][3]),
                          "r"(bf[ni][0]), "r"(bf[ni][1]));
        }
    };

    int s = 0;
    ldg_chunk(0);
    sts_chunk(0);
    __syncthreads();
    for (int c = 0; c < NC; c++) {
        if (c + 1 < NC) ldg_chunk(c + 1);
        compute(s);
        if (c + 1 < NC) sts_chunk(s ^ 1);
        __syncthreads();
        s ^= 1;
    }

    const float qscale = 0.17677669529663687f;

    auto store_pair = [&](int m, int n, float vx, float vy) {
        vx += __ldg(&bias[n]);
        vy += __ldg(&bias[n + 1]);
        if (MODE == 0) {
            int tq = n / CCH;
            int rem = n - tq * CCH;
            int head = rem >> 5, hd = rem & 31;
            int win = m / NTOK, tokn = m - win * NTOK;
            float scl = (tq == 0) ? qscale : 1.0f;
            float* dst = (tq == 0) ? g_q : (tq == 1) ? g_k : g_v;
            size_t o = (((size_t)(win * NHEAD + head)) * NTOK + tokn) * HDIM + hd;
            *reinterpret_cast<float2*>(dst + o) = make_float2(vx * scl, vy * scl);
        } else if (MODE == 1) {
            int win = m / NTOK, tokn = m - win * NTOK;
            int b = win >> 6, widx = win & 63;
            int h = (widx >> 3) * 7 + tokn / 7 + 3; if (h >= HH)  h -= HH;
            int w = (widx & 7) * 7 + tokn % 7 + 3;  if (w >= WW2) w -= WW2;
            int hw = h * WW2 + w;
            size_t tk = (size_t)b * (HH * WW2) + hw;
            float rx = __ldg(aux + ((size_t)b * CCH + n) * (HH * WW2) + hw);
            float ry = __ldg(aux + ((size_t)b * CCH + n + 1) * (HH * WW2) + hw);
            *reinterpret_cast<float2*>(g_x2 + tk * CCH + n) =
                make_float2(vx + rx, vy + ry);
        } else if (MODE == 2) {
            vx = 0.5f * vx * (1.0f + erff(vx * 0.70710678118654752f));
            vy = 0.5f * vy * (1.0f + erff(vy * 0.70710678118654752f));
            *reinterpret_cast<__nv_bfloat162*>(g_h1 + (size_t)m * MLPD + n) =
                __floats2bfloat162_rn(vx, vy);
        } else {
            float2 r = *reinterpret_cast<const float2*>(g_x2 + (size_t)m * CCH + n);
            int b = m / (HH * WW2), hw = m - b * (HH * WW2);
            aux[((size_t)b * CCH + n) * (HH * WW2) + hw] = vx + r.x;
            aux[((size_t)b * CCH + n + 1) * (HH * WW2) + hw] = vy + r.y;
        }
    };

#pragma unroll
    for (int mi = 0; mi < 4; mi++) {
#pragma unroll
        for (int ni = 0; ni < 4; ni++) {
            int m = m0 + wm * 64 + mi * 16 + gid;
            int n = n0 + wn * 32 + ni * 8 + tig * 2;
            store_pair(m,     n, acc[mi][ni][0], acc[mi][ni][1]);
            store_pair(m + 8, n, acc[mi][ni][2], acc[mi][ni][3]);
        }
    }
}

// ---------------------------------------------------------------------------
// K1: LN1 + NCHW->NHWC + shifted-window partition (bf16 out only)
// ---------------------------------------------------------------------------
__global__ void __launch_bounds__(256) k_ln1_window(
    const float* __restrict__ x, const float* __restrict__ g1,
    const float* __restrict__ b1)
{
    extern __shared__ float sm[];
    __shared__ float smu[56], srs[56];
    const int bh = blockIdx.x;
    const int b = bh / HH, h = bh % HH;
    const int tid = threadIdx.x;
    const int warp = tid >> 5, lane = tid & 31;
    const float* xp = x + (size_t)b * CCH * (HH * WW2) + (size_t)h * WW2;

    for (int idx = tid; idx < CCH * WW2; idx += 256) {
        int c = idx / WW2, w = idx % WW2;
        sm[c * 57 + w] = xp[(size_t)c * (HH * WW2) + w];
    }
    __syncthreads();

#pragma unroll
    for (int i = 0; i < 7; i++) {
        int w = warp * 7 + i;
        float s = 0.f, s2 = 0.f;
#pragma unroll
        for (int j = 0; j < 12; j++) {
            float t = sm[(lane + j * 32) * 57 + w];
            s += t; s2 += t * t;
        }
#pragma unroll
        for (int o = 16; o; o >>= 1) {
            s  += __shfl_xor_sync(0xffffffffu, s,  o);
            s2 += __shfl_xor_sync(0xffffffffu, s2, o);
        }
        if (lane == 0) {
            float mu = s * (1.0f / CCH);
            smu[w] = mu;
            srs[w] = rsqrtf(s2 * (1.0f / CCH) - mu * mu + 1e-5f);
        }
    }
    __syncthreads();

    int hp = h - 3; if (hp < 0) hp += HH;
    const int wh = hp / 7, rr = hp % 7;
    for (int idx = tid; idx < WW2 * CCH; idx += 256) {
        int w = idx / CCH, c = idx % CCH;
        float val = sm[c * 57 + w];
        float nv = (val - smu[w]) * srs[w] * __ldg(&g1[c]) + __ldg(&b1[c]);
        int wp = w - 3; if (wp < 0) wp += WW2;
        int win = (b * 8 + wh) * 8 + wp / 7;
        g_xw[((size_t)win * NTOK + rr * 7 + wp % 7) * CCH + c] =
            __float2bfloat16_rn(nv);
    }
}

// ---------------------------------------------------------------------------
// K3: windowed attention, float4-vectorized smem.
// QK^T: thread (ti=tid/13, tj=tid%13): rows ti*4..+3, cols {tj+13c},
//       float4 loads over headdim (stride-36 rows).
// PV: warp = 8 rows, sS broadcast float4, sv scalar (rows padded to 52).
// ---------------------------------------------------------------------------
__global__ void __launch_bounds__(256) k_attn()
{
    __shared__ __align__(16) float sq[52 * 36];
    __shared__ __align__(16) float sk[52 * 36];
    __shared__ float sv[52 * 33];
    __shared__ __align__(16) float sS[52 * 52];
    __shared__ int   sid[52];

    const int win = blockIdx.x / NHEAD;
    const int nh  = blockIdx.x % NHEAD;
    const int tid = threadIdx.x;
    const int warp = tid >> 5, lane = tid & 31;
    const size_t base = ((size_t)(win * NHEAD + nh)) * NTOK * HDIM;

    for (int idx = tid; idx < NTOK * HDIM; idx += 256) {
        int r = idx >> 5, c = idx & 31;
        sq[r * 36 + c] = g_q[base + idx];
        sk[r * 36 + c] = g_k[base + idx];
        sv[r * 33 + c] = g_v[base + idx];
    }
    for (int idx = tid; idx < 3 * 36; idx += 256) {
        sq[NTOK * 36 + idx] = 0.f;
        sk[NTOK * 36 + idx] = 0.f;
    }
    for (int idx = tid; idx < 3 * 33; idx += 256)
        sv[NTOK * 33 + idx] = 0.f;
    if (tid < 52) {
        int v = 0;
        if (tid < NTOK) {
            int widx = win & 63;
            int hp = (widx >> 3) * 7 + tid / 7;
            int wp = (widx & 7) * 7 + tid % 7;
            int hr = (hp < 49) ? 0 : (hp < 53 ? 1 : 2);
            int wr = (wp < 49) ? 0 : (wp < 53 ? 1 : 2);
            v = hr * 3 + wr;
        }
        sid[tid] = v;
    }
    __syncthreads();

    // ---- QK^T: 4x4 register tile, float4 smem loads ----
    if (tid < 169) {
        const int iq = (tid / 13) * 4;
        const int tj = tid % 13;
        float acc[4][4];
#pragma unroll
        for (int r = 0; r < 4; r++)
#pragma unroll
            for (int c = 0; c < 4; c++) acc[r][c] = 0.f;
#pragma unroll
        for (int l4 = 0; l4 < 8; l4++) {
            float4 qa[4], kb[4];
#pragma unroll
            for (int r = 0; r < 4; r++)
                qa[r] = *reinterpret_cast<const float4*>(
                    &sq[(iq + r) * 36 + l4 * 4]);
#pragma unroll
            for (int c = 0; c < 4; c++)
                kb[c] = *reinterpret_cast<const float4*>(
                    &sk[(tj + 13 * c) * 36 + l4 * 4]);
#pragma unroll
            for (int r = 0; r < 4; r++)
#pragma unroll
                for (int c = 0; c < 4; c++) {
                    acc[r][c] += qa[r].x * kb[c].x;
                    acc[r][c] += qa[r].y * kb[c].y;
                    acc[r][c] += qa[r].z * kb[c].z;
                    acc[r][c] += qa[r].w * kb[c].w;
                }
        }
#pragma unroll
        for (int r = 0; r < 4; r++)
#pragma unroll
            for (int c = 0; c < 4; c++) {
                int i = iq + r, j = tj + 13 * c;
                float sc = acc[r][c];
                if (sid[i] != sid[j]) sc -= 100.0f;
                sS[i * 52 + j] = sc;
            }
    }
    __syncthreads();

    // ---- softmax (rows 0..48) ----
    for (int i = warp; i < NTOK; i += 8) {
        float mx = -1e30f;
        for (int j = lane; j < NTOK; j += 32) mx = fmaxf(mx, sS[i * 52 + j]);
#pragma unroll
        for (int o = 16; o; o >>= 1) mx = fmaxf(mx, __shfl_xor_sync(0xffffffffu, mx, o));
        float sum = 0.f;
        for (int j = lane; j < NTOK; j += 32) {
            float e = __expf(sS[i * 52 + j] - mx);
            sS[i * 52 + j] = e;
            sum += e;
        }
#pragma unroll
        for (int o = 16; o; o >>= 1) sum += __shfl_xor_sync(0xffffffffu, sum, o);
        float inv = 1.0f / sum;
        for (int j = lane; j < NTOK; j += 32) sS[i * 52 + j] *= inv;
    }
    // zero pad cols 49..51 (all 52 rows) so PV float4 reads are clean
    for (int idx = tid; idx < 52 * 3; idx += 256)
        sS[(idx % 52) * 52 + 49 + idx / 52] = 0.f;
    __syncthreads();

    // ---- PV: warp = 8 rows x 32 dims, one pass, float4 sS broadcasts ----
    {
        const int r0 = warp * 8;
        if (r0 < NTOK) {
            float o[8];
#pragma unroll
            for (int r = 0; r < 8; r++) o[r] = 0.f;
            for (int j4 = 0; j4 < 13; j4++) {
                float v0 = sv[(j4 * 4 + 0) * 33 + lane];
                float v1 = sv[(j4 * 4 + 1) * 33 + lane];
                float v2 = sv[(j4 * 4 + 2) * 33 + lane];
                float v3 = sv[(j4 * 4 + 3) * 33 + lane];
#pragma unroll
                for (int r = 0; r < 8; r++) {
                    int row = r0 + r; if (row > 51) row = 51;  // clamp (unused rows)
                    float4 p = *reinterpret_cast<const float4*>(
                        &sS[row * 52 + j4 * 4]);
                    o[r] += p.x * v0;
                    o[r] += p.y * v1;
                    o[r] += p.z * v2;
                    o[r] += p.w * v3;
                }
            }
#pragma unroll
            for (int r = 0; r < 8; r++) {
                int i = r0 + r;
                if (i < NTOK)
                    g_ao[((size_t)(win * NTOK + i)) * CCH + nh * HDIM + lane] =
                        __float2bfloat16_rn(o[r]);
            }
        }
    }
}

// ---------------------------------------------------------------------------
// K4: LN2 (bf16 out)
// ---------------------------------------------------------------------------
__global__ void __launch_bounds__(256) k_ln2(
    const float* __restrict__ g2, const float* __restrict__ b2)
{
    const int warp = threadIdx.x >> 5, lane = threadIdx.x & 31;
    const size_t tok = (size_t)blockIdx.x * 8 + warp;
    const float* p = g_x2 + tok * CCH;
    float v[12];
    float s = 0.f, s2 = 0.f;
#pragma unroll
    for (int i = 0; i < 12; i++) {
        v[i] = p[lane + i * 32];
        s += v[i]; s2 += v[i] * v[i];
    }
#pragma unroll
    for (int o = 16; o; o >>= 1) {
        s  += __shfl_xor_sync(0xffffffffu, s,  o);
        s2 += __shfl_xor_sync(0xffffffffu, s2, o);
    }
    float mu = s * (1.0f / CCH);
    float rs = rsqrtf(s2 * (1.0f / CCH) - mu * mu + 1e-5f);
    __nv_bfloat16* q = g_xn2 + tok * CCH;
#pragma unroll
    for (int i = 0; i < 12; i++) {
        int c = lane + i * 32;
        q[c] = __float2bfloat16_rn(
            (v[i] - mu) * rs * __ldg(&g2[c]) + __ldg(&b2[c]));
    }
}

// ---------------------------------------------------------------------------
extern "C" void kernel_launch(void* const* d_in, const int* in_sizes, int n_in,
                              void* d_out, int out_size)
{
    const float* x       = (const float*)d_in[0];
    const float* norm1_g = (const float*)d_in[1];
    const float* norm1_b = (const float*)d_in[2];
    const float* qkv_w   = (const float*)d_in[3];
    const float* qkv_b   = (const float*)d_in[4];
    const float* proj_w  = (const float*)d_in[5];
    const float* proj_b  = (const float*)d_in[6];
    const float* norm2_g = (const float*)d_in[7];
    const float* norm2_b = (const float*)d_in[8];
    const float* fc1_w   = (const float*)d_in[9];
    const float* fc1_b   = (const float*)d_in[10];
    const float* fc2_w   = (const float*)d_in[11];
    const float* fc2_b   = (const float*)d_in[12];

    __nv_bfloat16 *p_xw, *p_ao, *p_xn2, *p_h1;
    __nv_bfloat16 *p_wqkv, *p_wproj, *p_wfc1, *p_wfc2;
    cudaGetSymbolAddress((void**)&p_xw,   g_xw);
    cudaGetSymbolAddress((void**)&p_ao,   g_ao);
    cudaGetSymbolAddress((void**)&p_xn2,  g_xn2);
    cudaGetSymbolAddress((void**)&p_h1,   g_h1);
    cudaGetSymbolAddress((void**)&p_wqkv, g_wt_qkv);
    cudaGetSymbolAddress((void**)&p_wproj,g_wt_proj);
    cudaGetSymbolAddress((void**)&p_wfc1, g_wt_fc1);
    cudaGetSymbolAddress((void**)&p_wfc2, g_wt_fc2);

    const int ln1_smem = 384 * 57 * sizeof(float);
    cudaFuncSetAttribute(k_ln1_window,
                         cudaFuncAttributeMaxDynamicSharedMemorySize, ln1_smem);

    // 0) merged weight prep
    k_wtprep_all<<<dim3(48, 48, 4), 256>>>(qkv_w, proj_w, fc1_w, fc2_w);

    // 1) LN1 + transpose + shifted window partition
    k_ln1_window<<<16 * HH, 256, ln1_smem>>>(x, norm1_g, norm1_b);

    // 2) QKV GEMM
    k_gemm_bf16<0><<<dim3(1152 / 128, TOK / 128), 256>>>(
        p_xw, p_wqkv, qkv_b, nullptr, 384, 1152, 12);

    // 3) windowed attention
    k_attn<<<NWIN * NHEAD, 256>>>();

    // 4) proj GEMM + window reverse + residual from x (NCHW)
    k_gemm_bf16<1><<<dim3(CCH / 128, TOK / 128), 256>>>(
        p_ao, p_wproj, proj_b, (float*)x, 384, CCH, 12);

    // 5) LN2
    k_ln2<<<TOK / 8, 256>>>(norm2_g, norm2_b);

    // 6) fc1 + GELU
    k_gemm_bf16<2><<<dim3(MLPD / 128, TOK / 128), 256>>>(
        p_xn2, p_wfc1, fc1_b, nullptr, 384, MLPD, 12);

    // 7) fc2 + residual -> NCHW output directly
    k_gemm_bf16<3><<<dim3(CCH / 128, TOK / 128), 256>>>(
        p_h1, p_wfc2, fc2_b, (float*)d_out, 1536, CCH, 48);
}